// round 13
// baseline (speedup 1.0000x reference)
#include <cuda_runtime.h>
#include <cuda_bf16.h>
#include <math.h>
#include <stdint.h>

#define HW   16384
#define NB   4
#define DD   256
#define KP   128          // DD/2 k-pairs
#define NR   32
#define NS   64
#define NC2  128
#define NSEL 160
#define NPART 512
#define INVTAU 10.0f

// ---------------- scratch ----------------
__device__ float g_x[NB * DD * HW];
__device__ unsigned int g_bh[(size_t)NB * KP * HW];   // packed bf16 hi pairs of feat
__device__ unsigned int g_blo[(size_t)NB * KP * HW];  // packed bf16 lo pairs of feat
__device__ unsigned int g_ah[KP * DD];                // packed bf16 hi pairs of w1
__device__ unsigned int g_alo[KP * DD];               // packed bf16 lo pairs of w1
__device__ float g_psum[NPART * DD];
__device__ float g_psq [NPART * DD];
__device__ float g_scale[DD];
__device__ float g_shift[DD];
__device__ unsigned char g_mask[NB * HW];
__device__ int   g_cntA[NB * 2];
__device__ int   g_cntN[NB * 2];
__device__ int   g_aidx[NB * 2 * NR];
__device__ float g_aw  [NB * 2 * NR];
__device__ int   g_pidx[NB * 2 * NS];
__device__ float g_pw  [NB * 2 * NS];
__device__ int   g_nidx[NB * 2 * NS];
__device__ float g_nw  [NB * 2 * NS];
__device__ float g_bl  [NB * 2];
__device__ int   g_inc [NB * 2];
__device__ float g_syf [NB * DD];
__device__ float g_syb [NB * DD];
__device__ float g_w2t [DD * DD];
__device__ float g_psel[NB * 2 * NSEL * DD];

// ---------------- helpers ----------------
__device__ __forceinline__ float warpSumF(float v) {
#pragma unroll
    for (int o = 16; o; o >>= 1) v += __shfl_xor_sync(0xffffffffu, v, o);
    return v;
}
__device__ __forceinline__ unsigned int ford(float f) {
    unsigned int u = __float_as_uint(f);
    return (u & 0x80000000u) ? ~u : (u | 0x80000000u);
}
__device__ __forceinline__ unsigned int packb(__nv_bfloat16 x, __nv_bfloat16 y) {
    __nv_bfloat162 t; t.x = x; t.y = y;
    return *reinterpret_cast<unsigned int*>(&t);
}
__device__ __forceinline__ void bsplit(float v, __nv_bfloat16& h, __nv_bfloat16& l) {
    h = __float2bfloat16_rn(v);
    l = __float2bfloat16_rn(v - __bfloat162float(h));
}
// pack hi/lo pairs from two fp32 values (consecutive k)
__device__ __forceinline__ void pairsplit(float a, float b,
                                          unsigned int& ph, unsigned int& pl) {
    __nv_bfloat16 h0, l0, h1, l1;
    bsplit(a, h0, l0);
    bsplit(b, h1, l1);
    ph = packb(h0, h1);
    pl = packb(l0, l1);
}

#define MMA_BF16(c, a, b)                                                        \
    asm volatile("mma.sync.aligned.m16n8k16.row.col.f32.bf16.bf16.f32 "          \
                 "{%0,%1,%2,%3}, {%4,%5,%6,%7}, {%8,%9}, {%0,%1,%2,%3};\n"       \
                 : "+f"((c)[0]), "+f"((c)[1]), "+f"((c)[2]), "+f"((c)[3])        \
                 : "r"((a)[0]), "r"((a)[1]), "r"((a)[2]), "r"((a)[3]),           \
                   "r"((b)[0]), "r"((b)[1]))

// ---------------- pre-split kernels ----------------
__global__ void __launch_bounds__(256) w1split_k(const float* __restrict__ w1)
{
    const int kp = blockIdx.x;       // 0..127
    const int m = threadIdx.x;       // 0..255
    unsigned int ph, pl;
    pairsplit(w1[m * DD + 2 * kp], w1[m * DD + 2 * kp + 1], ph, pl);
    g_ah [kp * DD + m] = ph;
    g_alo[kp * DD + m] = pl;
}

__global__ void __launch_bounds__(256) bsplit_k(const float* __restrict__ feat)
{
    const int b = blockIdx.z, kp = blockIdx.y;
    const int n = (blockIdx.x * 256 + threadIdx.x) * 4;
    const float* r0 = feat + (size_t)(b * DD + 2 * kp) * HW;
    const float* r1 = r0 + HW;
    float4 v0 = *(const float4*)&r0[n];
    float4 v1 = *(const float4*)&r1[n];
    uint4 h, l;
    pairsplit(v0.x, v1.x, h.x, l.x);
    pairsplit(v0.y, v1.y, h.y, l.y);
    pairsplit(v0.z, v1.z, h.z, l.z);
    pairsplit(v0.w, v1.w, h.w, l.w);
    size_t off = (size_t)(b * KP + kp) * HW + n;
    *(uint4*)&g_bh [off] = h;
    *(uint4*)&g_blo[off] = l;
}

// ================= GEMM1 (3xBF16 split, pre-split operands) + BN partials ====
#define SSTRB 136
__global__ void __launch_bounds__(256) gemm1_k(
    const float* __restrict__ bias, float* __restrict__ C)
{
    __shared__ unsigned int Ah[8][SSTRB], Al[8][SSTRB];
    __shared__ unsigned int Bh[8][SSTRB], Bl[8][SSTRB];
    __shared__ float redS[2][64][4], redQ[2][64][4];

    const int bb = blockIdx.z;
    const int n0 = blockIdx.x * 128;
    const int m0 = blockIdx.y * 128;
    const int tid = threadIdx.x;
    const int wid = tid >> 5, lane = tid & 31;
    const int wm = wid >> 2, wn = wid & 3;
    const int g = lane >> 2, tg = lane & 3;

    // staging: thread -> kp-row (0..7), 4 consecutive columns
    const int sr = tid >> 5;
    const int scv = (tid & 31) * 4;
    const size_t bbase = (size_t)(bb * KP) * HW;

    float c[4][4][4] = {};
    uint4 pAh, pAl, pBh, pBl;

    pAh = *(const uint4*)&g_ah [(0 + sr) * DD + m0 + scv];
    pAl = *(const uint4*)&g_alo[(0 + sr) * DD + m0 + scv];
    pBh = *(const uint4*)&g_bh [bbase + (size_t)(0 + sr) * HW + n0 + scv];
    pBl = *(const uint4*)&g_blo[bbase + (size_t)(0 + sr) * HW + n0 + scv];

    for (int k0 = 0; k0 < DD; k0 += 16) {
        // ---- stage ----
        *(uint4*)&Ah[sr][scv] = pAh;
        *(uint4*)&Al[sr][scv] = pAl;
        *(uint4*)&Bh[sr][scv] = pBh;
        *(uint4*)&Bl[sr][scv] = pBl;
        __syncthreads();
        // ---- prefetch next slab ----
        if (k0 + 16 < DD) {
            int kp0 = (k0 + 16) >> 1;
            pAh = *(const uint4*)&g_ah [(kp0 + sr) * DD + m0 + scv];
            pAl = *(const uint4*)&g_alo[(kp0 + sr) * DD + m0 + scv];
            pBh = *(const uint4*)&g_bh [bbase + (size_t)(kp0 + sr) * HW + n0 + scv];
            pBl = *(const uint4*)&g_blo[bbase + (size_t)(kp0 + sr) * HW + n0 + scv];
        }
        // ---- fragments + MMA ----
        {
            unsigned int ah[4][4], alr[4][4], bhf[4][2], blf[4][2];
#pragma unroll
            for (int i = 0; i < 4; i++) {
                int m = wm * 64 + i * 16 + g;
                ah[i][0] = Ah[tg][m];     ah[i][1] = Ah[tg][m + 8];
                ah[i][2] = Ah[tg + 4][m]; ah[i][3] = Ah[tg + 4][m + 8];
                alr[i][0] = Al[tg][m];     alr[i][1] = Al[tg][m + 8];
                alr[i][2] = Al[tg + 4][m]; alr[i][3] = Al[tg + 4][m + 8];
            }
#pragma unroll
            for (int j = 0; j < 4; j++) {
                int n = wn * 32 + j * 8 + g;
                bhf[j][0] = Bh[tg][n]; bhf[j][1] = Bh[tg + 4][n];
                blf[j][0] = Bl[tg][n]; blf[j][1] = Bl[tg + 4][n];
            }
#pragma unroll
            for (int i = 0; i < 4; i++)
#pragma unroll
                for (int j = 0; j < 4; j++) {
                    MMA_BF16(c[i][j], ah[i], bhf[j]);
                    MMA_BF16(c[i][j], ah[i], blf[j]);
                    MMA_BF16(c[i][j], alr[i], bhf[j]);
                }
        }
        __syncthreads();
    }
    // ---- epilogue: bias + store + BN partials ----
#pragma unroll
    for (int i = 0; i < 4; i++) {
        int m = m0 + wm * 64 + i * 16 + g;
        float bs0 = bias[m], bs1 = bias[m + 8];
#pragma unroll
        for (int j = 0; j < 4; j++) {
            c[i][j][0] += bs0; c[i][j][1] += bs0;
            c[i][j][2] += bs1; c[i][j][3] += bs1;
            int n = n0 + wn * 32 + j * 8 + 2 * tg;
            float2 o0 = {c[i][j][0], c[i][j][1]};
            float2 o1 = {c[i][j][2], c[i][j][3]};
            *(float2*)&C[(size_t)(bb * DD + m) * HW + n] = o0;
            *(float2*)&C[(size_t)(bb * DD + m + 8) * HW + n] = o1;
        }
    }
#pragma unroll
    for (int i = 0; i < 4; i++) {
        float s0 = 0.f, s1 = 0.f, q0 = 0.f, q1 = 0.f;
#pragma unroll
        for (int j = 0; j < 4; j++) {
            s0 += c[i][j][0] + c[i][j][1];
            q0 += c[i][j][0] * c[i][j][0] + c[i][j][1] * c[i][j][1];
            s1 += c[i][j][2] + c[i][j][3];
            q1 += c[i][j][2] * c[i][j][2] + c[i][j][3] * c[i][j][3];
        }
#pragma unroll
        for (int o = 1; o <= 2; o <<= 1) {
            s0 += __shfl_xor_sync(0xffffffffu, s0, o);
            s1 += __shfl_xor_sync(0xffffffffu, s1, o);
            q0 += __shfl_xor_sync(0xffffffffu, q0, o);
            q1 += __shfl_xor_sync(0xffffffffu, q1, o);
        }
        if (tg == 0) {
            redS[wm][i * 16 + g][wn] = s0;
            redS[wm][i * 16 + g + 8][wn] = s1;
            redQ[wm][i * 16 + g][wn] = q0;
            redQ[wm][i * 16 + g + 8][wn] = q1;
        }
    }
    __syncthreads();
    if (tid < 128) {
        int wmx = tid >> 6, r = tid & 63;
        float s = redS[wmx][r][0] + redS[wmx][r][1] + redS[wmx][r][2] + redS[wmx][r][3];
        float q = redQ[wmx][r][0] + redQ[wmx][r][1] + redQ[wmx][r][2] + redQ[wmx][r][3];
        int pidx = blockIdx.z * 128 + blockIdx.x;
        g_psum[pidx * DD + m0 + tid] = s;
        g_psq [pidx * DD + m0 + tid] = q;
    }
}

// ---------------- BN scale/shift ----------------
__global__ void __launch_bounds__(128) bnscale_k(const float* __restrict__ gamma,
                                                 const float* __restrict__ beta)
{
    __shared__ float ssh[4], qsh[4];
    const int e = blockIdx.x;
    float s = 0.f, q = 0.f;
    for (int p = threadIdx.x; p < NPART; p += 128) {
        s += g_psum[p * DD + e];
        q += g_psq [p * DD + e];
    }
    int lane = threadIdx.x & 31, w = threadIdx.x >> 5;
    s = warpSumF(s); q = warpSumF(q);
    if (lane == 0) { ssh[w] = s; qsh[w] = q; }
    __syncthreads();
    if (threadIdx.x == 0) {
        float ts = ssh[0] + ssh[1] + ssh[2] + ssh[3];
        float tq = qsh[0] + qsh[1] + qsh[2] + qsh[3];
        const float inv_n = 1.f / (float)(NB * HW);
        float mean = ts * inv_n;
        float var  = tq * inv_n - mean * mean;
        float sc = gamma[e] * rsqrtf(var + 1e-5f);
        g_scale[e] = sc;
        g_shift[e] = beta[e] - mean * sc;
    }
}

// ---------------- masks ----------------
__global__ void mask_k(const int* __restrict__ labels, const float* __restrict__ po,
                       const float* __restrict__ pa, const float* __restrict__ unc)
{
    int i = blockIdx.x * blockDim.x + threadIdx.x;
    if (i >= NB * HW) return;
    int b = i >> 14, hw = i & (HW - 1);
    const float* o = po + (size_t)b * 2 * HW;
    const float* a = pa + (size_t)b * 2 * HW;
    int ao = (o[HW + hw] > o[hw]) ? 1 : 0;
    int aa = (a[HW + hw] > a[hw]) ? 1 : 0;
    bool valid = (ao == aa) && (unc[i] > 0.5f);
    unsigned char m = 0;
    if (valid) m = (labels[i] == 1) ? 1 : 2;
    g_mask[i] = m;
}

// ---------------- masked sums of y ----------------
__global__ void __launch_bounds__(256) ymask_k()
{
    __shared__ float s1[8], s2[8];
    const int d = blockIdx.x, b = blockIdx.y;
    const float* row = g_x + (size_t)(b * DD + d) * HW;
    const unsigned char* mk = g_mask + b * HW;
    const float sc = g_scale[d], sh = g_shift[d];
    float sf = 0.f, sb = 0.f;
    for (int i = threadIdx.x; i < HW; i += 256) {
        float y = fmaxf(fmaf(sc, row[i], sh), 0.f);
        unsigned char m = mk[i];
        sf += (m == 1) ? y : 0.f;
        sb += (m == 2) ? y : 0.f;
    }
    int lane = threadIdx.x & 31, w = threadIdx.x >> 5;
    sf = warpSumF(sf); sb = warpSumF(sb);
    if (lane == 0) { s1[w] = sf; s2[w] = sb; }
    __syncthreads();
    if (threadIdx.x == 0) {
        float a = 0.f, bb = 0.f;
        for (int i = 0; i < 8; i++) { a += s1[i]; bb += s2[i]; }
        g_syf[b * DD + d] = a;
        g_syb[b * DD + d] = bb;
    }
}

// ---------------- w2 transpose ----------------
__global__ void w2t_k(const float* __restrict__ w2)
{
    int k = blockIdx.x, m = threadIdx.x;
    g_w2t[k * DD + m] = w2[m * DD + k];
}

// ================= selection: radix top-k ==========
struct SelShared {
    int hist[256];
    int warp_tot[17];
    int s_bin, s_rem, s_ngt, s_fill, s_mcnt;
    int sel_idx[NC2];
    unsigned int sel_key[NC2];
    int cand_idx[NC2];
    float cand_w[NC2];
    unsigned long long sbuf[NC2];
};

__device__ __forceinline__ int blk_scan(int pred, int* warp_tot, int tid, int* tot) {
    unsigned bal = __ballot_sync(0xffffffffu, pred);
    int lane = tid & 31, w = tid >> 5;
    if (lane == 0) warp_tot[w] = __popc(bal);
    __syncthreads();
    if (tid == 0) {
        int s = 0;
        for (int i = 0; i < 16; i++) { int t = warp_tot[i]; warp_tot[i] = s; s += t; }
        warp_tot[16] = s;
    }
    __syncthreads();
    int rank = warp_tot[w] + __popc(bal & ((1u << lane) - 1));
    *tot = warp_tot[16];
    __syncthreads();
    return rank;
}

__device__ void topk_sel(unsigned int* skey, int k, SelShared* sh, int tid, bool want_cnt) {
    unsigned int prefix = 0;
    if (tid == 0) sh->s_rem = k;
    __syncthreads();
#pragma unroll
    for (int level = 0; level < 4; level++) {
        int shift = 24 - 8 * level;
        if (tid < 256) sh->hist[tid] = 0;
        __syncthreads();
        for (int i = tid; i < HW; i += 512) {
            unsigned int v = skey[i];
            bool in = (level == 0) || ((v >> (shift + 8)) == prefix);
            if (in) atomicAdd(&sh->hist[(v >> shift) & 255], 1);
        }
        __syncthreads();
        if (tid == 0) {
            if (level == 0 && want_cnt) {
                int mc = 0;
                for (int b = 128; b < 256; b++) mc += sh->hist[b];
                sh->s_mcnt = mc;
            }
            int need = sh->s_rem;
            int c = 0, b;
            for (b = 255; b >= 0; --b) {
                int h = sh->hist[b];
                if (c + h >= need) break;
                c += h;
            }
            sh->s_bin = b;
            sh->s_rem = need - c;
        }
        __syncthreads();
        prefix = (prefix << 8) | (unsigned int)sh->s_bin;
        __syncthreads();
    }
    const unsigned int T = prefix;
    const int rem = sh->s_rem;
    if (tid == 0) sh->s_ngt = 0;
    __syncthreads();
    for (int i = tid; i < HW; i += 512) {
        unsigned int v = skey[i];
        if (v > T) {
            int p = atomicAdd(&sh->s_ngt, 1);
            sh->sel_idx[p] = i;
            sh->sel_key[p] = v;
        }
    }
    __syncthreads();
    const int cgt = sh->s_ngt;
    if (tid == 0) sh->s_fill = 0;
    __syncthreads();
    if (rem > 0) {
        for (int base = 0; base < HW; base += 512) {
            int i = base + tid;
            int pred = (skey[i] == T) ? 1 : 0;
            int tot;
            int rank = blk_scan(pred, sh->warp_tot, tid, &tot);
            int fl = sh->s_fill;
            if (pred && fl + rank < rem) {
                sh->sel_idx[cgt + fl + rank] = i;
                sh->sel_key[cgt + fl + rank] = T;
            }
            __syncthreads();
            if (tid == 0) sh->s_fill += tot;
            __syncthreads();
            if (sh->s_fill >= rem) break;
            __syncthreads();
        }
    }
    __syncthreads();
}

__device__ void bitonic128(unsigned long long* buf, int tid) {
    for (int ksz = 2; ksz <= 128; ksz <<= 1)
        for (int j = ksz >> 1; j > 0; j >>= 1) {
            __syncthreads();
            if (tid < 64) {
                int i = ((tid / j) * (j << 1)) + (tid & (j - 1));
                int ixj = i + j;
                bool up = ((i & ksz) == 0);
                unsigned long long x = buf[i], y = buf[ixj];
                if ((x > y) == up) { buf[i] = y; buf[ixj] = x; }
            }
        }
    __syncthreads();
}

// blockIdx.x = bc*3 + phase; phase 0 = anchors, 1 = pos, 2 = neg
__global__ void __launch_bounds__(512) select3_k(
    const float* __restrict__ r_anc, const float* __restrict__ r_pos,
    const float* __restrict__ r_neg, const float* __restrict__ unc)
{
    extern __shared__ unsigned int skey[];
    __shared__ SelShared sh;
    const int bc = blockIdx.x / 3, phase = blockIdx.x - bc * 3;
    const int b = bc >> 1, c = bc & 1;
    const unsigned char wantA = (c == 0) ? 1 : 2;
    const unsigned char wantN = (c == 0) ? 2 : 1;
    const unsigned char* mk = g_mask + b * HW;
    const int tid = threadIdx.x;

    if (phase == 0) {
        const float* r = r_anc + (size_t)bc * HW;
        for (int i = tid; i < HW; i += 512)
            skey[i] = (mk[i] == wantA) ? ford(r[i]) : 0u;
        __syncthreads();
        topk_sel(skey, NR, &sh, tid, true);
        if (tid == 0) g_cntA[bc] = sh.s_mcnt;
        if (tid < NR) {
            g_aidx[bc * NR + tid] = sh.sel_idx[tid];
            g_aw  [bc * NR + tid] = (sh.sel_key[tid] >= 0x80000000u) ? 1.f : 0.f;
        }
        return;
    }

    const int ph = phase - 1;
    const unsigned char want = ph ? wantN : wantA;
    const float* r = (ph ? r_neg : r_pos) + (size_t)bc * HW;
    for (int i = tid; i < HW; i += 512)
        skey[i] = (mk[i] == want) ? ford(r[i]) : 0u;
    __syncthreads();
    topk_sel(skey, NC2, &sh, tid, ph == 1);
    if (ph == 1 && tid == 0) g_cntN[bc] = sh.s_mcnt;
    if (tid < NC2)
        sh.sbuf[tid] = ((unsigned long long)sh.sel_key[tid] << 32) |
                       (unsigned int)(~sh.sel_idx[tid]);
    __syncthreads();
    bitonic128(sh.sbuf, tid);
    if (tid < NC2) {
        unsigned long long e = sh.sbuf[127 - tid];
        int idx = (int)(~(unsigned int)(e & 0xFFFFFFFFu));
        unsigned int kv = (unsigned int)(e >> 32);
        sh.cand_idx[tid] = idx;
        sh.cand_w[tid] = (kv >= 0x80000000u) ? 1.f : 0.f;
    }
    __syncthreads();
    if (tid < NC2) {
        unsigned int uk = (sh.cand_w[tid] > 0.f)
                        ? ford(unc[b * HW + sh.cand_idx[tid]]) : 0u;
        sh.sbuf[tid] = ((unsigned long long)uk << 32) |
                       (unsigned int)(0xFFFFFFFFu - (unsigned int)tid);
    }
    __syncthreads();
    bitonic128(sh.sbuf, tid);
    int*   oidx = ph ? g_nidx : g_pidx;
    float* ow   = ph ? g_nw   : g_pw;
    if (tid < NS) {
        unsigned long long e = sh.sbuf[127 - tid];
        int t = (int)(0xFFFFFFFFu - (unsigned int)(e & 0xFFFFFFFFu));
        oidx[bc * NS + tid] = sh.cand_idx[t];
        ow  [bc * NS + tid] = sh.cand_w[t];
    }
}

// ---------------- project selected pixels ----------------
__global__ void __launch_bounds__(256) psel_k(const float* __restrict__ b2)
{
    __shared__ float ys[4][DD];
    const int bc = blockIdx.y, b = bc >> 1;
    const int col0 = blockIdx.x * 4;
    const int tid = threadIdx.x;
    const float sc = g_scale[tid], sh = g_shift[tid];
#pragma unroll
    for (int cc = 0; cc < 4; cc++) {
        int col = col0 + cc;
        int idx;
        if (col < 32)      idx = g_aidx[bc * NR + col];
        else if (col < 96) idx = g_pidx[bc * NS + col - 32];
        else               idx = g_nidx[bc * NS + col - 96];
        float x = g_x[(size_t)(b * DD + tid) * HW + idx];
        ys[cc][tid] = fmaxf(fmaf(sc, x, sh), 0.f);
    }
    __syncthreads();
    float acc0, acc1, acc2, acc3;
    acc0 = acc1 = acc2 = acc3 = b2[tid];
    for (int k = 0; k < DD; k++) {
        float w = g_w2t[k * DD + tid];
        acc0 = fmaf(w, ys[0][k], acc0);
        acc1 = fmaf(w, ys[1][k], acc1);
        acc2 = fmaf(w, ys[2][k], acc2);
        acc3 = fmaf(w, ys[3][k], acc3);
    }
    float* outp = g_psel + ((size_t)bc * NSEL + col0) * DD;
    outp[0 * DD + tid] = acc0;
    outp[1 * DD + tid] = acc1;
    outp[2 * DD + tid] = acc2;
    outp[3 * DD + tid] = acc3;
}

// ---------------- pair loss ----------------
__global__ void __launch_bounds__(256) pair_k()
{
    __shared__ float q[NR][DD];
    __shared__ float pnw[8][NR];
    const int bc = blockIdx.x;
    const int tid = threadIdx.x, lane = tid & 31, w = tid >> 5;
    const float* ps = g_psel + (size_t)bc * NSEL * DD;

    for (int a = w; a < NR; a += 8) {
        float vv[8]; float ss = 0.f;
#pragma unroll
        for (int j = 0; j < 8; j++) {
            float v = ps[a * DD + lane + 32 * j];
            vv[j] = v; ss = fmaf(v, v, ss);
        }
        ss = warpSumF(ss);
        float inv = 1.f / fmaxf(sqrtf(ss), 1e-12f);
#pragma unroll
        for (int j = 0; j < 8; j++) q[a][lane + 32 * j] = vv[j] * inv;
    }
    pnw[w][lane] = 0.f;
    __syncthreads();

    const int ph = w >> 2, lw = w & 3;
    const float* wl = ph ? g_nw : g_pw;
    const int colbase = ph ? 96 : 32;
    for (int t = 0; t < 16; t++) {
        int s = lw * 16 + t;
        const float* vp = ps + (colbase + s) * DD;
        float vv[8]; float ss = 0.f;
#pragma unroll
        for (int j = 0; j < 8; j++) {
            float v = vp[lane + 32 * j];
            vv[j] = v; ss = fmaf(v, v, ss);
        }
        ss = warpSumF(ss);
        float inv = 1.f / fmaxf(sqrtf(ss), 1e-12f);
        float wt = wl[bc * NS + s];
#pragma unroll
        for (int a = 0; a < NR; a++) {
            float ds = 0.f;
#pragma unroll
            for (int j = 0; j < 8; j++)
                ds = fmaf(vv[j], q[a][lane + 32 * j], ds);
            ds = warpSumF(ds);
            if (lane == 0) pnw[w][a] += expf(ds * inv * INVTAU) * wt;
        }
    }
    __syncthreads();

    if (tid < 32) {
        int inc = (g_cntA[bc] >= 1 && g_cntN[bc] >= 1) ? 1 : 0;
        float p = pnw[0][tid] + pnw[1][tid] + pnw[2][tid] + pnw[3][tid]
                + (inc ? 0.f : 1.f);
        float n = pnw[4][tid] + pnw[5][tid] + pnw[6][tid] + pnw[7][tid];
        float per = -logf(p / (p + n + 1e-8f));
        float af = g_aw[bc * NR + tid];
        float num = warpSumF(per * af);
        float den = warpSumF(af);
        if (tid == 0) {
            float bl = num / fmaxf(den, 1.f);
            g_bl[bc] = inc ? bl : 0.f;
            g_inc[bc] = inc;
        }
    }
}

// ---------------- final ----------------
__global__ void __launch_bounds__(256) final_k(const float* __restrict__ b2,
                                               float* __restrict__ out)
{
    __shared__ float sy[8][DD];
    __shared__ float qv[8][DD];
    __shared__ float selfd[8], Xs[16];
    __shared__ float cfa[NB], cba[NB];
    __shared__ int vg[NB];
    const int tid = threadIdx.x, lane = tid & 31, w = tid >> 5;

    if (tid < NB) {
        int a = g_cntA[tid * 2], bb = g_cntN[tid * 2];
        cfa[tid] = (float)a; cba[tid] = (float)bb;
        vg[tid] = (a >= 1 && bb >= 1) ? 1 : 0;
    }
    __syncthreads();
#pragma unroll
    for (int v = 0; v < 8; v++) {
        int s = v >> 2, b = v & 3;
        float cnt = s ? cba[b] : cfa[b];
        const float* src = s ? (g_syb + b * DD) : (g_syf + b * DD);
        sy[v][tid] = src[tid] / fmaxf(cnt, 1.f);
    }
    __syncthreads();
    float acc[8];
    float bv = b2[tid];
#pragma unroll
    for (int v = 0; v < 8; v++) acc[v] = bv;
    for (int k = 0; k < DD; k++) {
        float wv = g_w2t[k * DD + tid];
#pragma unroll
        for (int v = 0; v < 8; v++) acc[v] = fmaf(wv, sy[v][k], acc[v]);
    }
#pragma unroll
    for (int v = 0; v < 8; v++) qv[v][tid] = acc[v];
    __syncthreads();
    {
        float ss = 0.f;
#pragma unroll
        for (int j = 0; j < 8; j++) {
            float x = qv[w][lane + 32 * j];
            ss = fmaf(x, x, ss);
        }
        ss = warpSumF(ss);
        float inv = 1.f / fmaxf(sqrtf(ss), 1e-12f);
#pragma unroll
        for (int j = 0; j < 8; j++) qv[w][lane + 32 * j] *= inv;
        __syncwarp();
        float s2 = 0.f;
#pragma unroll
        for (int j = 0; j < 8; j++) {
            float x = qv[w][lane + 32 * j];
            s2 = fmaf(x, x, s2);
        }
        s2 = warpSumF(s2);
        if (lane == 0) selfd[w] = s2;
    }
    __syncthreads();
    for (int pi = w; pi < 16; pi += 8) {
        int j = pi >> 2, b = pi & 3;
        float ds = 0.f;
#pragma unroll
        for (int jj = 0; jj < 8; jj++)
            ds = fmaf(qv[4 + j][lane + 32 * jj], qv[b][lane + 32 * jj], ds);
        ds = warpSumF(ds);
        if (lane == 0) Xs[pi] = ds;
    }
    __syncthreads();
    if (tid == 0) {
        float lg_sum = 0.f; int vg_cnt = 0;
        for (int b = 0; b < NB; b++) {
            float nf = 0.f, nbv = 0.f;
            for (int j = 0; j <= b; j++)
                if (vg[j]) {
                    nf  += expf(Xs[j * 4 + b] * INVTAU);
                    nbv += expf(Xs[b * 4 + j] * INVTAU);
                }
            float pf = expf(selfd[b] * INVTAU);
            float pb = expf(selfd[4 + b] * INVTAU);
            float lg = -logf(pf / (pf + nf + 1e-8f)) - logf(pb / (pb + nbv + 1e-8f));
            if (vg[b]) { lg_sum += lg; vg_cnt++; }
        }
        float l_global = lg_sum / fmaxf((float)vg_cnt, 1.f);
        float bl_sum = 0.f; int inc_cnt = 0;
        for (int i = 0; i < NB * 2; i++) { bl_sum += g_bl[i]; inc_cnt += g_inc[i]; }
        float l_local = bl_sum / fmaxf((float)inc_cnt, 1.f);
        out[0] = l_local + 0.5f * l_global;
        out[1] = l_local;
        out[2] = l_global;
    }
}

// ---------------- launch ----------------
extern "C" void kernel_launch(void* const* d_in, const int* in_sizes, int n_in,
                              void* d_out, int out_size)
{
    const float* feat   = (const float*)d_in[0];
    const int*   labels = (const int*)  d_in[1];
    const float* po     = (const float*)d_in[2];
    const float* pa     = (const float*)d_in[3];
    const float* unc    = (const float*)d_in[4];
    const float* r_anc  = (const float*)d_in[5];
    const float* r_pos  = (const float*)d_in[6];
    const float* r_neg  = (const float*)d_in[7];
    const float* w1     = (const float*)d_in[8];
    const float* b1     = (const float*)d_in[9];
    const float* gamma  = (const float*)d_in[10];
    const float* beta   = (const float*)d_in[11];
    const float* w2     = (const float*)d_in[12];
    const float* b2     = (const float*)d_in[13];
    float* out = (float*)d_out;

    static cudaStream_t s2 = nullptr;
    static cudaEvent_t evRoot = nullptr, evM = nullptr, evMask = nullptr, evJ2 = nullptr;
    if (!s2) {
        cudaStreamCreateWithFlags(&s2, cudaStreamNonBlocking);
        cudaEventCreateWithFlags(&evRoot, cudaEventDisableTiming);
        cudaEventCreateWithFlags(&evM, cudaEventDisableTiming);
        cudaEventCreateWithFlags(&evMask, cudaEventDisableTiming);
        cudaEventCreateWithFlags(&evJ2, cudaEventDisableTiming);
        cudaFuncSetAttribute(select3_k, cudaFuncAttributeMaxDynamicSharedMemorySize,
                             HW * (int)sizeof(unsigned int));
    }

    void* px = nullptr;
    cudaGetSymbolAddress(&px, g_x);

    // fork side stream
    cudaEventRecord(evRoot, 0);
    cudaStreamWaitEvent(s2, evRoot, 0);

    // main stream: pre-split -> GEMM -> BN reduce
    w1split_k<<<KP, 256>>>(w1);
    bsplit_k<<<dim3(HW / 1024, KP, NB), 256>>>(feat);
    gemm1_k<<<dim3(HW / 128, DD / 128, NB), 256>>>(b1, (float*)px);
    bnscale_k<<<DD, 128>>>(gamma, beta);
    cudaEventRecord(evM, 0);

    // side stream: input-only chain, then selected-pixel projection + pair loss
    mask_k<<<(NB * HW + 255) / 256, 256, 0, s2>>>(labels, po, pa, unc);
    cudaEventRecord(evMask, s2);
    select3_k<<<NB * 2 * 3, 512, HW * (int)sizeof(unsigned int), s2>>>(r_anc, r_pos, r_neg, unc);
    w2t_k<<<DD, DD, 0, s2>>>(w2);
    cudaStreamWaitEvent(s2, evM, 0);
    psel_k<<<dim3(NSEL / 4, NB * 2), 256, 0, s2>>>(b2);
    pair_k<<<NB * 2, 256, 0, s2>>>();
    cudaEventRecord(evJ2, s2);

    // main stream: masked sums (overlaps psel/pair), then final combine
    cudaStreamWaitEvent(0, evMask, 0);
    ymask_k<<<dim3(DD, NB), 256>>>();
    cudaStreamWaitEvent(0, evJ2, 0);
    final_k<<<1, 256>>>(b2, out);
}

// round 15
// speedup vs baseline: 1.0304x; 1.0304x over previous
#include <cuda_runtime.h>
#include <cuda_bf16.h>
#include <math.h>
#include <stdint.h>

#define HW   16384
#define NB   4
#define DD   256
#define NR   32
#define NS   64
#define NC2  128
#define NSEL 160
#define NPART 512
#define INVTAU 10.0f

// ---------------- scratch ----------------
__device__ float g_x[NB * DD * HW];
__device__ float g_psum[NPART * DD];
__device__ float g_psq [NPART * DD];
__device__ float g_scale[DD];
__device__ float g_shift[DD];
__device__ unsigned char g_mask[NB * HW];
__device__ int   g_cntA[NB * 2];
__device__ int   g_cntN[NB * 2];
__device__ int   g_aidx[NB * 2 * NR];
__device__ float g_aw  [NB * 2 * NR];
__device__ int   g_pidx[NB * 2 * NS];
__device__ float g_pw  [NB * 2 * NS];
__device__ int   g_nidx[NB * 2 * NS];
__device__ float g_nw  [NB * 2 * NS];
__device__ float g_bl  [NB * 2];
__device__ int   g_inc [NB * 2];
__device__ float g_syf [NB * DD];
__device__ float g_syb [NB * DD];
__device__ float g_w2t [DD * DD];
__device__ float g_psel[NB * 2 * NSEL * DD];

// ---------------- helpers ----------------
__device__ __forceinline__ float warpSumF(float v) {
#pragma unroll
    for (int o = 16; o; o >>= 1) v += __shfl_xor_sync(0xffffffffu, v, o);
    return v;
}
__device__ __forceinline__ unsigned int ford(float f) {
    unsigned int u = __float_as_uint(f);
    return (u & 0x80000000u) ? ~u : (u | 0x80000000u);
}
__device__ __forceinline__ unsigned int packb(__nv_bfloat16 x, __nv_bfloat16 y) {
    __nv_bfloat162 t; t.x = x; t.y = y;
    return *reinterpret_cast<unsigned int*>(&t);
}
__device__ __forceinline__ void bsplit(float v, __nv_bfloat16& h, __nv_bfloat16& l) {
    h = __float2bfloat16_rn(v);
    l = __float2bfloat16_rn(v - __bfloat162float(h));
}

#define MMA_BF16(c, a, b)                                                        \
    asm volatile("mma.sync.aligned.m16n8k16.row.col.f32.bf16.bf16.f32 "          \
                 "{%0,%1,%2,%3}, {%4,%5,%6,%7}, {%8,%9}, {%0,%1,%2,%3};\n"       \
                 : "+f"((c)[0]), "+f"((c)[1]), "+f"((c)[2]), "+f"((c)[3])        \
                 : "r"((a)[0]), "r"((a)[1]), "r"((a)[2]), "r"((a)[3]),           \
                   "r"((b)[0]), "r"((b)[1]))

// ======== GEMM1 (3xBF16 split, double-buffered smem) + BN partials ===========
#define SSTRB 136
__global__ void __launch_bounds__(256) gemm1_k(
    const float* __restrict__ A, const float* __restrict__ Bsrc,
    const float* __restrict__ bias, float* __restrict__ C)
{
    __shared__ unsigned int Ah[2][8][SSTRB], Al[2][8][SSTRB];
    __shared__ unsigned int Bh[2][8][SSTRB], Bl[2][8][SSTRB];
    __shared__ float redS[2][64][4], redQ[2][64][4];

    const int bb = blockIdx.z;
    const int n0 = blockIdx.x * 128;
    const int m0 = blockIdx.y * 128;
    const float* Bp = Bsrc + (size_t)bb * DD * HW;
    const int tid = threadIdx.x;
    const int wid = tid >> 5, lane = tid & 31;
    const int wm = wid >> 2, wn = wid & 3;
    const int g = lane >> 2, tg = lane & 3;

    const int arow = tid >> 1, ak2 = (tid & 1) * 4;
    const int br = tid >> 5;

    float c[4][4][4] = {};
    float4 pa0, pa1;
    float bB0[4], bB1[4];

    // load slab 0
    pa0 = *(const float4*)&A[(m0 + arow) * DD + ak2 * 2];
    pa1 = *(const float4*)&A[(m0 + arow) * DD + ak2 * 2 + 4];
#pragma unroll
    for (int q = 0; q < 4; q++) {
        bB0[q] = Bp[(size_t)(2 * br) * HW + n0 + lane + 32 * q];
        bB1[q] = Bp[(size_t)(2 * br + 1) * HW + n0 + lane + 32 * q];
    }
    // stage slab 0 into buffer 0
    {
        float av[8] = {pa0.x, pa0.y, pa0.z, pa0.w, pa1.x, pa1.y, pa1.z, pa1.w};
#pragma unroll
        for (int p = 0; p < 4; p++) {
            __nv_bfloat16 h0, l0, h1, l1;
            bsplit(av[2 * p], h0, l0);
            bsplit(av[2 * p + 1], h1, l1);
            Ah[0][ak2 + p][arow] = packb(h0, h1);
            Al[0][ak2 + p][arow] = packb(l0, l1);
        }
#pragma unroll
        for (int q = 0; q < 4; q++) {
            __nv_bfloat16 h0, l0, h1, l1;
            bsplit(bB0[q], h0, l0);
            bsplit(bB1[q], h1, l1);
            Bh[0][br][lane + 32 * q] = packb(h0, h1);
            Bl[0][br][lane + 32 * q] = packb(l0, l1);
        }
    }
    __syncthreads();

    int cur = 0;
    for (int k0 = 0; k0 < DD; k0 += 16) {
        const bool more = (k0 + 16 < DD);
        // ---- issue global loads for next slab (latency hidden under MMAs) ----
        if (more) {
            pa0 = *(const float4*)&A[(m0 + arow) * DD + k0 + 16 + ak2 * 2];
            pa1 = *(const float4*)&A[(m0 + arow) * DD + k0 + 16 + ak2 * 2 + 4];
#pragma unroll
            for (int q = 0; q < 4; q++) {
                bB0[q] = Bp[(size_t)(k0 + 16 + 2 * br) * HW + n0 + lane + 32 * q];
                bB1[q] = Bp[(size_t)(k0 + 16 + 2 * br + 1) * HW + n0 + lane + 32 * q];
            }
        }
        // ---- compute from buffer cur ----
        {
            unsigned int ah[4][4], alr[4][4], bhf[4][2], blf[4][2];
#pragma unroll
            for (int i = 0; i < 4; i++) {
                int m = wm * 64 + i * 16 + g;
                ah[i][0] = Ah[cur][tg][m];     ah[i][1] = Ah[cur][tg][m + 8];
                ah[i][2] = Ah[cur][tg + 4][m]; ah[i][3] = Ah[cur][tg + 4][m + 8];
                alr[i][0] = Al[cur][tg][m];     alr[i][1] = Al[cur][tg][m + 8];
                alr[i][2] = Al[cur][tg + 4][m]; alr[i][3] = Al[cur][tg + 4][m + 8];
            }
#pragma unroll
            for (int j = 0; j < 4; j++) {
                int n = wn * 32 + j * 8 + g;
                bhf[j][0] = Bh[cur][tg][n]; bhf[j][1] = Bh[cur][tg + 4][n];
                blf[j][0] = Bl[cur][tg][n]; blf[j][1] = Bl[cur][tg + 4][n];
            }
#pragma unroll
            for (int i = 0; i < 4; i++)
#pragma unroll
                for (int j = 0; j < 4; j++) {
                    MMA_BF16(c[i][j], ah[i], bhf[j]);
                    MMA_BF16(c[i][j], ah[i], blf[j]);
                    MMA_BF16(c[i][j], alr[i], bhf[j]);
                }
        }
        // ---- stage next slab into the other buffer ----
        if (more) {
            int nxt = cur ^ 1;
            float av[8] = {pa0.x, pa0.y, pa0.z, pa0.w, pa1.x, pa1.y, pa1.z, pa1.w};
#pragma unroll
            for (int p = 0; p < 4; p++) {
                __nv_bfloat16 h0, l0, h1, l1;
                bsplit(av[2 * p], h0, l0);
                bsplit(av[2 * p + 1], h1, l1);
                Ah[nxt][ak2 + p][arow] = packb(h0, h1);
                Al[nxt][ak2 + p][arow] = packb(l0, l1);
            }
#pragma unroll
            for (int q = 0; q < 4; q++) {
                __nv_bfloat16 h0, l0, h1, l1;
                bsplit(bB0[q], h0, l0);
                bsplit(bB1[q], h1, l1);
                Bh[nxt][br][lane + 32 * q] = packb(h0, h1);
                Bl[nxt][br][lane + 32 * q] = packb(l0, l1);
            }
            __syncthreads();
            cur = nxt;
        }
    }
    // ---- epilogue: bias + store + BN partials ----
#pragma unroll
    for (int i = 0; i < 4; i++) {
        int m = m0 + wm * 64 + i * 16 + g;
        float bs0 = bias[m], bs1 = bias[m + 8];
#pragma unroll
        for (int j = 0; j < 4; j++) {
            c[i][j][0] += bs0; c[i][j][1] += bs0;
            c[i][j][2] += bs1; c[i][j][3] += bs1;
            int n = n0 + wn * 32 + j * 8 + 2 * tg;
            float2 o0 = {c[i][j][0], c[i][j][1]};
            float2 o1 = {c[i][j][2], c[i][j][3]};
            *(float2*)&C[(size_t)(bb * DD + m) * HW + n] = o0;
            *(float2*)&C[(size_t)(bb * DD + m + 8) * HW + n] = o1;
        }
    }
#pragma unroll
    for (int i = 0; i < 4; i++) {
        float s0 = 0.f, s1 = 0.f, q0 = 0.f, q1 = 0.f;
#pragma unroll
        for (int j = 0; j < 4; j++) {
            s0 += c[i][j][0] + c[i][j][1];
            q0 += c[i][j][0] * c[i][j][0] + c[i][j][1] * c[i][j][1];
            s1 += c[i][j][2] + c[i][j][3];
            q1 += c[i][j][2] * c[i][j][2] + c[i][j][3] * c[i][j][3];
        }
#pragma unroll
        for (int o = 1; o <= 2; o <<= 1) {
            s0 += __shfl_xor_sync(0xffffffffu, s0, o);
            s1 += __shfl_xor_sync(0xffffffffu, s1, o);
            q0 += __shfl_xor_sync(0xffffffffu, q0, o);
            q1 += __shfl_xor_sync(0xffffffffu, q1, o);
        }
        if (tg == 0) {
            redS[wm][i * 16 + g][wn] = s0;
            redS[wm][i * 16 + g + 8][wn] = s1;
            redQ[wm][i * 16 + g][wn] = q0;
            redQ[wm][i * 16 + g + 8][wn] = q1;
        }
    }
    __syncthreads();
    if (tid < 128) {
        int wmx = tid >> 6, r = tid & 63;
        float s = redS[wmx][r][0] + redS[wmx][r][1] + redS[wmx][r][2] + redS[wmx][r][3];
        float q = redQ[wmx][r][0] + redQ[wmx][r][1] + redQ[wmx][r][2] + redQ[wmx][r][3];
        int pidx = blockIdx.z * 128 + blockIdx.x;
        g_psum[pidx * DD + m0 + tid] = s;
        g_psq [pidx * DD + m0 + tid] = q;
    }
}

// ---------------- BN scale/shift ----------------
__global__ void __launch_bounds__(128) bnscale_k(const float* __restrict__ gamma,
                                                 const float* __restrict__ beta)
{
    __shared__ float ssh[4], qsh[4];
    const int e = blockIdx.x;
    float s = 0.f, q = 0.f;
    for (int p = threadIdx.x; p < NPART; p += 128) {
        s += g_psum[p * DD + e];
        q += g_psq [p * DD + e];
    }
    int lane = threadIdx.x & 31, w = threadIdx.x >> 5;
    s = warpSumF(s); q = warpSumF(q);
    if (lane == 0) { ssh[w] = s; qsh[w] = q; }
    __syncthreads();
    if (threadIdx.x == 0) {
        float ts = ssh[0] + ssh[1] + ssh[2] + ssh[3];
        float tq = qsh[0] + qsh[1] + qsh[2] + qsh[3];
        const float inv_n = 1.f / (float)(NB * HW);
        float mean = ts * inv_n;
        float var  = tq * inv_n - mean * mean;
        float sc = gamma[e] * rsqrtf(var + 1e-5f);
        g_scale[e] = sc;
        g_shift[e] = beta[e] - mean * sc;
    }
}

// ---------------- masks ----------------
__global__ void mask_k(const int* __restrict__ labels, const float* __restrict__ po,
                       const float* __restrict__ pa, const float* __restrict__ unc)
{
    int i = blockIdx.x * blockDim.x + threadIdx.x;
    if (i >= NB * HW) return;
    int b = i >> 14, hw = i & (HW - 1);
    const float* o = po + (size_t)b * 2 * HW;
    const float* a = pa + (size_t)b * 2 * HW;
    int ao = (o[HW + hw] > o[hw]) ? 1 : 0;
    int aa = (a[HW + hw] > a[hw]) ? 1 : 0;
    bool valid = (ao == aa) && (unc[i] > 0.5f);
    unsigned char m = 0;
    if (valid) m = (labels[i] == 1) ? 1 : 2;
    g_mask[i] = m;
}

// ---------------- masked sums of y ----------------
__global__ void __launch_bounds__(256) ymask_k()
{
    __shared__ float s1[8], s2[8];
    const int d = blockIdx.x, b = blockIdx.y;
    const float* row = g_x + (size_t)(b * DD + d) * HW;
    const unsigned char* mk = g_mask + b * HW;
    const float sc = g_scale[d], sh = g_shift[d];
    float sf = 0.f, sb = 0.f;
    for (int i = threadIdx.x; i < HW; i += 256) {
        float y = fmaxf(fmaf(sc, row[i], sh), 0.f);
        unsigned char m = mk[i];
        sf += (m == 1) ? y : 0.f;
        sb += (m == 2) ? y : 0.f;
    }
    int lane = threadIdx.x & 31, w = threadIdx.x >> 5;
    sf = warpSumF(sf); sb = warpSumF(sb);
    if (lane == 0) { s1[w] = sf; s2[w] = sb; }
    __syncthreads();
    if (threadIdx.x == 0) {
        float a = 0.f, bb = 0.f;
        for (int i = 0; i < 8; i++) { a += s1[i]; bb += s2[i]; }
        g_syf[b * DD + d] = a;
        g_syb[b * DD + d] = bb;
    }
}

// ---------------- w2 transpose ----------------
__global__ void w2t_k(const float* __restrict__ w2)
{
    int k = blockIdx.x, m = threadIdx.x;
    g_w2t[k * DD + m] = w2[m * DD + k];
}

// ================= selection: radix top-k ==========
struct SelShared {
    int hist[256];
    int warp_tot[17];
    int s_bin, s_rem, s_ngt, s_fill, s_mcnt;
    int sel_idx[NC2];
    unsigned int sel_key[NC2];
    int cand_idx[NC2];
    float cand_w[NC2];
    unsigned long long sbuf[NC2];
};

__device__ __forceinline__ int blk_scan(int pred, int* warp_tot, int tid, int* tot) {
    unsigned bal = __ballot_sync(0xffffffffu, pred);
    int lane = tid & 31, w = tid >> 5;
    if (lane == 0) warp_tot[w] = __popc(bal);
    __syncthreads();
    if (tid == 0) {
        int s = 0;
        for (int i = 0; i < 16; i++) { int t = warp_tot[i]; warp_tot[i] = s; s += t; }
        warp_tot[16] = s;
    }
    __syncthreads();
    int rank = warp_tot[w] + __popc(bal & ((1u << lane) - 1));
    *tot = warp_tot[16];
    __syncthreads();
    return rank;
}

__device__ void topk_sel(unsigned int* skey, int k, SelShared* sh, int tid, bool want_cnt) {
    unsigned int prefix = 0;
    if (tid == 0) sh->s_rem = k;
    __syncthreads();
#pragma unroll
    for (int level = 0; level < 4; level++) {
        int shift = 24 - 8 * level;
        if (tid < 256) sh->hist[tid] = 0;
        __syncthreads();
        for (int i = tid; i < HW; i += 512) {
            unsigned int v = skey[i];
            bool in = (level == 0) || ((v >> (shift + 8)) == prefix);
            if (in) atomicAdd(&sh->hist[(v >> shift) & 255], 1);
        }
        __syncthreads();
        if (tid == 0) {
            if (level == 0 && want_cnt) {
                int mc = 0;
                for (int b = 128; b < 256; b++) mc += sh->hist[b];
                sh->s_mcnt = mc;
            }
            int need = sh->s_rem;
            int c = 0, b;
            for (b = 255; b >= 0; --b) {
                int h = sh->hist[b];
                if (c + h >= need) break;
                c += h;
            }
            sh->s_bin = b;
            sh->s_rem = need - c;
        }
        __syncthreads();
        prefix = (prefix << 8) | (unsigned int)sh->s_bin;
        __syncthreads();
    }
    const unsigned int T = prefix;
    const int rem = sh->s_rem;
    if (tid == 0) sh->s_ngt = 0;
    __syncthreads();
    for (int i = tid; i < HW; i += 512) {
        unsigned int v = skey[i];
        if (v > T) {
            int p = atomicAdd(&sh->s_ngt, 1);
            sh->sel_idx[p] = i;
            sh->sel_key[p] = v;
        }
    }
    __syncthreads();
    const int cgt = sh->s_ngt;
    if (tid == 0) sh->s_fill = 0;
    __syncthreads();
    if (rem > 0) {
        for (int base = 0; base < HW; base += 512) {
            int i = base + tid;
            int pred = (skey[i] == T) ? 1 : 0;
            int tot;
            int rank = blk_scan(pred, sh->warp_tot, tid, &tot);
            int fl = sh->s_fill;
            if (pred && fl + rank < rem) {
                sh->sel_idx[cgt + fl + rank] = i;
                sh->sel_key[cgt + fl + rank] = T;
            }
            __syncthreads();
            if (tid == 0) sh->s_fill += tot;
            __syncthreads();
            if (sh->s_fill >= rem) break;
            __syncthreads();
        }
    }
    __syncthreads();
}

__device__ void bitonic128(unsigned long long* buf, int tid) {
    for (int ksz = 2; ksz <= 128; ksz <<= 1)
        for (int j = ksz >> 1; j > 0; j >>= 1) {
            __syncthreads();
            if (tid < 64) {
                int i = ((tid / j) * (j << 1)) + (tid & (j - 1));
                int ixj = i + j;
                bool up = ((i & ksz) == 0);
                unsigned long long x = buf[i], y = buf[ixj];
                if ((x > y) == up) { buf[i] = y; buf[ixj] = x; }
            }
        }
    __syncthreads();
}

// blockIdx.x = bc*3 + phase; phase 0 = anchors, 1 = pos, 2 = neg
__global__ void __launch_bounds__(512) select3_k(
    const float* __restrict__ r_anc, const float* __restrict__ r_pos,
    const float* __restrict__ r_neg, const float* __restrict__ unc)
{
    extern __shared__ unsigned int skey[];
    __shared__ SelShared sh;
    const int bc = blockIdx.x / 3, phase = blockIdx.x - bc * 3;
    const int b = bc >> 1, c = bc & 1;
    const unsigned char wantA = (c == 0) ? 1 : 2;
    const unsigned char wantN = (c == 0) ? 2 : 1;
    const unsigned char* mk = g_mask + b * HW;
    const int tid = threadIdx.x;

    if (phase == 0) {
        const float* r = r_anc + (size_t)bc * HW;
        for (int i = tid; i < HW; i += 512)
            skey[i] = (mk[i] == wantA) ? ford(r[i]) : 0u;
        __syncthreads();
        topk_sel(skey, NR, &sh, tid, true);
        if (tid == 0) g_cntA[bc] = sh.s_mcnt;
        if (tid < NR) {
            g_aidx[bc * NR + tid] = sh.sel_idx[tid];
            g_aw  [bc * NR + tid] = (sh.sel_key[tid] >= 0x80000000u) ? 1.f : 0.f;
        }
        return;
    }

    const int ph = phase - 1;
    const unsigned char want = ph ? wantN : wantA;
    const float* r = (ph ? r_neg : r_pos) + (size_t)bc * HW;
    for (int i = tid; i < HW; i += 512)
        skey[i] = (mk[i] == want) ? ford(r[i]) : 0u;
    __syncthreads();
    topk_sel(skey, NC2, &sh, tid, ph == 1);
    if (ph == 1 && tid == 0) g_cntN[bc] = sh.s_mcnt;
    if (tid < NC2)
        sh.sbuf[tid] = ((unsigned long long)sh.sel_key[tid] << 32) |
                       (unsigned int)(~sh.sel_idx[tid]);
    __syncthreads();
    bitonic128(sh.sbuf, tid);
    if (tid < NC2) {
        unsigned long long e = sh.sbuf[127 - tid];
        int idx = (int)(~(unsigned int)(e & 0xFFFFFFFFu));
        unsigned int kv = (unsigned int)(e >> 32);
        sh.cand_idx[tid] = idx;
        sh.cand_w[tid] = (kv >= 0x80000000u) ? 1.f : 0.f;
    }
    __syncthreads();
    if (tid < NC2) {
        unsigned int uk = (sh.cand_w[tid] > 0.f)
                        ? ford(unc[b * HW + sh.cand_idx[tid]]) : 0u;
        sh.sbuf[tid] = ((unsigned long long)uk << 32) |
                       (unsigned int)(0xFFFFFFFFu - (unsigned int)tid);
    }
    __syncthreads();
    bitonic128(sh.sbuf, tid);
    int*   oidx = ph ? g_nidx : g_pidx;
    float* ow   = ph ? g_nw   : g_pw;
    if (tid < NS) {
        unsigned long long e = sh.sbuf[127 - tid];
        int t = (int)(0xFFFFFFFFu - (unsigned int)(e & 0xFFFFFFFFu));
        oidx[bc * NS + tid] = sh.cand_idx[t];
        ow  [bc * NS + tid] = sh.cand_w[t];
    }
}

// ---------------- project selected pixels ----------------
__global__ void __launch_bounds__(256) psel_k(const float* __restrict__ b2)
{
    __shared__ float ys[4][DD];
    const int bc = blockIdx.y, b = bc >> 1;
    const int col0 = blockIdx.x * 4;
    const int tid = threadIdx.x;
    const float sc = g_scale[tid], sh = g_shift[tid];
#pragma unroll
    for (int cc = 0; cc < 4; cc++) {
        int col = col0 + cc;
        int idx;
        if (col < 32)      idx = g_aidx[bc * NR + col];
        else if (col < 96) idx = g_pidx[bc * NS + col - 32];
        else               idx = g_nidx[bc * NS + col - 96];
        float x = g_x[(size_t)(b * DD + tid) * HW + idx];
        ys[cc][tid] = fmaxf(fmaf(sc, x, sh), 0.f);
    }
    __syncthreads();
    float acc0, acc1, acc2, acc3;
    acc0 = acc1 = acc2 = acc3 = b2[tid];
    for (int k = 0; k < DD; k++) {
        float w = g_w2t[k * DD + tid];
        acc0 = fmaf(w, ys[0][k], acc0);
        acc1 = fmaf(w, ys[1][k], acc1);
        acc2 = fmaf(w, ys[2][k], acc2);
        acc3 = fmaf(w, ys[3][k], acc3);
    }
    float* outp = g_psel + ((size_t)bc * NSEL + col0) * DD;
    outp[0 * DD + tid] = acc0;
    outp[1 * DD + tid] = acc1;
    outp[2 * DD + tid] = acc2;
    outp[3 * DD + tid] = acc3;
}

// ---------------- pair loss ----------------
__global__ void __launch_bounds__(256) pair_k()
{
    __shared__ float q[NR][DD];
    __shared__ float pnw[8][NR];
    const int bc = blockIdx.x;
    const int tid = threadIdx.x, lane = tid & 31, w = tid >> 5;
    const float* ps = g_psel + (size_t)bc * NSEL * DD;

    for (int a = w; a < NR; a += 8) {
        float vv[8]; float ss = 0.f;
#pragma unroll
        for (int j = 0; j < 8; j++) {
            float v = ps[a * DD + lane + 32 * j];
            vv[j] = v; ss = fmaf(v, v, ss);
        }
        ss = warpSumF(ss);
        float inv = 1.f / fmaxf(sqrtf(ss), 1e-12f);
#pragma unroll
        for (int j = 0; j < 8; j++) q[a][lane + 32 * j] = vv[j] * inv;
    }
    pnw[w][lane] = 0.f;
    __syncthreads();

    const int ph = w >> 2, lw = w & 3;
    const float* wl = ph ? g_nw : g_pw;
    const int colbase = ph ? 96 : 32;
    for (int t = 0; t < 16; t++) {
        int s = lw * 16 + t;
        const float* vp = ps + (colbase + s) * DD;
        float vv[8]; float ss = 0.f;
#pragma unroll
        for (int j = 0; j < 8; j++) {
            float v = vp[lane + 32 * j];
            vv[j] = v; ss = fmaf(v, v, ss);
        }
        ss = warpSumF(ss);
        float inv = 1.f / fmaxf(sqrtf(ss), 1e-12f);
        float wt = wl[bc * NS + s];
#pragma unroll
        for (int a = 0; a < NR; a++) {
            float ds = 0.f;
#pragma unroll
            for (int j = 0; j < 8; j++)
                ds = fmaf(vv[j], q[a][lane + 32 * j], ds);
            ds = warpSumF(ds);
            if (lane == 0) pnw[w][a] += expf(ds * inv * INVTAU) * wt;
        }
    }
    __syncthreads();

    if (tid < 32) {
        int inc = (g_cntA[bc] >= 1 && g_cntN[bc] >= 1) ? 1 : 0;
        float p = pnw[0][tid] + pnw[1][tid] + pnw[2][tid] + pnw[3][tid]
                + (inc ? 0.f : 1.f);
        float n = pnw[4][tid] + pnw[5][tid] + pnw[6][tid] + pnw[7][tid];
        float per = -logf(p / (p + n + 1e-8f));
        float af = g_aw[bc * NR + tid];
        float num = warpSumF(per * af);
        float den = warpSumF(af);
        if (tid == 0) {
            float bl = num / fmaxf(den, 1.f);
            g_bl[bc] = inc ? bl : 0.f;
            g_inc[bc] = inc;
        }
    }
}

// ---------------- final ----------------
__global__ void __launch_bounds__(256) final_k(const float* __restrict__ b2,
                                               float* __restrict__ out)
{
    __shared__ float sy[8][DD];
    __shared__ float qv[8][DD];
    __shared__ float selfd[8], Xs[16];
    __shared__ float cfa[NB], cba[NB];
    __shared__ int vg[NB];
    const int tid = threadIdx.x, lane = tid & 31, w = tid >> 5;

    if (tid < NB) {
        int a = g_cntA[tid * 2], bb = g_cntN[tid * 2];
        cfa[tid] = (float)a; cba[tid] = (float)bb;
        vg[tid] = (a >= 1 && bb >= 1) ? 1 : 0;
    }
    __syncthreads();
#pragma unroll
    for (int v = 0; v < 8; v++) {
        int s = v >> 2, b = v & 3;
        float cnt = s ? cba[b] : cfa[b];
        const float* src = s ? (g_syb + b * DD) : (g_syf + b * DD);
        sy[v][tid] = src[tid] / fmaxf(cnt, 1.f);
    }
    __syncthreads();
    float acc[8];
    float bv = b2[tid];
#pragma unroll
    for (int v = 0; v < 8; v++) acc[v] = bv;
    for (int k = 0; k < DD; k++) {
        float wv = g_w2t[k * DD + tid];
#pragma unroll
        for (int v = 0; v < 8; v++) acc[v] = fmaf(wv, sy[v][k], acc[v]);
    }
#pragma unroll
    for (int v = 0; v < 8; v++) qv[v][tid] = acc[v];
    __syncthreads();
    {
        float ss = 0.f;
#pragma unroll
        for (int j = 0; j < 8; j++) {
            float x = qv[w][lane + 32 * j];
            ss = fmaf(x, x, ss);
        }
        ss = warpSumF(ss);
        float inv = 1.f / fmaxf(sqrtf(ss), 1e-12f);
#pragma unroll
        for (int j = 0; j < 8; j++) qv[w][lane + 32 * j] *= inv;
        __syncwarp();
        float s2 = 0.f;
#pragma unroll
        for (int j = 0; j < 8; j++) {
            float x = qv[w][lane + 32 * j];
            s2 = fmaf(x, x, s2);
        }
        s2 = warpSumF(s2);
        if (lane == 0) selfd[w] = s2;
    }
    __syncthreads();
    for (int pi = w; pi < 16; pi += 8) {
        int j = pi >> 2, b = pi & 3;
        float ds = 0.f;
#pragma unroll
        for (int jj = 0; jj < 8; jj++)
            ds = fmaf(qv[4 + j][lane + 32 * jj], qv[b][lane + 32 * jj], ds);
        ds = warpSumF(ds);
        if (lane == 0) Xs[pi] = ds;
    }
    __syncthreads();
    if (tid == 0) {
        float lg_sum = 0.f; int vg_cnt = 0;
        for (int b = 0; b < NB; b++) {
            float nf = 0.f, nbv = 0.f;
            for (int j = 0; j <= b; j++)
                if (vg[j]) {
                    nf  += expf(Xs[j * 4 + b] * INVTAU);
                    nbv += expf(Xs[b * 4 + j] * INVTAU);
                }
            float pf = expf(selfd[b] * INVTAU);
            float pb = expf(selfd[4 + b] * INVTAU);
            float lg = -logf(pf / (pf + nf + 1e-8f)) - logf(pb / (pb + nbv + 1e-8f));
            if (vg[b]) { lg_sum += lg; vg_cnt++; }
        }
        float l_global = lg_sum / fmaxf((float)vg_cnt, 1.f);
        float bl_sum = 0.f; int inc_cnt = 0;
        for (int i = 0; i < NB * 2; i++) { bl_sum += g_bl[i]; inc_cnt += g_inc[i]; }
        float l_local = bl_sum / fmaxf((float)inc_cnt, 1.f);
        out[0] = l_local + 0.5f * l_global;
        out[1] = l_local;
        out[2] = l_global;
    }
}

// ---------------- launch ----------------
extern "C" void kernel_launch(void* const* d_in, const int* in_sizes, int n_in,
                              void* d_out, int out_size)
{
    const float* feat   = (const float*)d_in[0];
    const int*   labels = (const int*)  d_in[1];
    const float* po     = (const float*)d_in[2];
    const float* pa     = (const float*)d_in[3];
    const float* unc    = (const float*)d_in[4];
    const float* r_anc  = (const float*)d_in[5];
    const float* r_pos  = (const float*)d_in[6];
    const float* r_neg  = (const float*)d_in[7];
    const float* w1     = (const float*)d_in[8];
    const float* b1     = (const float*)d_in[9];
    const float* gamma  = (const float*)d_in[10];
    const float* beta   = (const float*)d_in[11];
    const float* w2     = (const float*)d_in[12];
    const float* b2     = (const float*)d_in[13];
    float* out = (float*)d_out;

    static cudaStream_t s2 = nullptr;
    static cudaEvent_t evRoot = nullptr, evM = nullptr, evMask = nullptr, evJ2 = nullptr;
    if (!s2) {
        cudaStreamCreateWithFlags(&s2, cudaStreamNonBlocking);
        cudaEventCreateWithFlags(&evRoot, cudaEventDisableTiming);
        cudaEventCreateWithFlags(&evM, cudaEventDisableTiming);
        cudaEventCreateWithFlags(&evMask, cudaEventDisableTiming);
        cudaEventCreateWithFlags(&evJ2, cudaEventDisableTiming);
        cudaFuncSetAttribute(select3_k, cudaFuncAttributeMaxDynamicSharedMemorySize,
                             HW * (int)sizeof(unsigned int));
    }

    void* px = nullptr;
    cudaGetSymbolAddress(&px, g_x);

    // fork side stream
    cudaEventRecord(evRoot, 0);
    cudaStreamWaitEvent(s2, evRoot, 0);

    // main stream: GEMM + BN reduce
    gemm1_k<<<dim3(HW / 128, DD / 128, NB), 256>>>(w1, feat, b1, (float*)px);
    bnscale_k<<<DD, 128>>>(gamma, beta);
    cudaEventRecord(evM, 0);

    // side stream: input-only chain, then selected-pixel projection + pair loss
    mask_k<<<(NB * HW + 255) / 256, 256, 0, s2>>>(labels, po, pa, unc);
    cudaEventRecord(evMask, s2);
    select3_k<<<NB * 2 * 3, 512, HW * (int)sizeof(unsigned int), s2>>>(r_anc, r_pos, r_neg, unc);
    w2t_k<<<DD, DD, 0, s2>>>(w2);
    cudaStreamWaitEvent(s2, evM, 0);
    psel_k<<<dim3(NSEL / 4, NB * 2), 256, 0, s2>>>(b2);
    pair_k<<<NB * 2, 256, 0, s2>>>();
    cudaEventRecord(evJ2, s2);

    // main stream: masked sums (overlaps psel/pair), then final combine
    cudaStreamWaitEvent(0, evMask, 0);
    ymask_k<<<dim3(DD, NB), 256>>>();
    cudaStreamWaitEvent(0, evJ2, 0);
    final_k<<<1, 256>>>(b2, out);
}

// round 16
// speedup vs baseline: 1.0410x; 1.0103x over previous
#include <cuda_runtime.h>
#include <cuda_bf16.h>
#include <math.h>
#include <stdint.h>

#define HW   16384
#define NB   4
#define DD   256
#define NR   32
#define NS   64
#define NC2  128
#define NSEL 160
#define NPART 512
#define INVTAU 10.0f

// ---------------- scratch ----------------
__device__ float g_x[NB * DD * HW];
__device__ float g_psum[NPART * DD];
__device__ float g_psq [NPART * DD];
__device__ float g_scale[DD];
__device__ float g_shift[DD];
__device__ unsigned char g_mask[NB * HW];
__device__ int   g_cntA[NB * 2];
__device__ int   g_cntN[NB * 2];
__device__ int   g_aidx[NB * 2 * NR];
__device__ float g_aw  [NB * 2 * NR];
__device__ int   g_pidx[NB * 2 * NS];
__device__ float g_pw  [NB * 2 * NS];
__device__ int   g_nidx[NB * 2 * NS];
__device__ float g_nw  [NB * 2 * NS];
__device__ float g_bl  [NB * 2];
__device__ int   g_inc [NB * 2];
__device__ float g_syf [NB * DD];
__device__ float g_syb [NB * DD];
__device__ float g_w2t [DD * DD];
__device__ float g_psel[NB * 2 * NSEL * DD];

// ---------------- helpers ----------------
__device__ __forceinline__ float warpSumF(float v) {
#pragma unroll
    for (int o = 16; o; o >>= 1) v += __shfl_xor_sync(0xffffffffu, v, o);
    return v;
}
__device__ __forceinline__ unsigned int ford(float f) {
    unsigned int u = __float_as_uint(f);
    return (u & 0x80000000u) ? ~u : (u | 0x80000000u);
}
__device__ __forceinline__ unsigned int packb(__nv_bfloat16 x, __nv_bfloat16 y) {
    __nv_bfloat162 t; t.x = x; t.y = y;
    return *reinterpret_cast<unsigned int*>(&t);
}
__device__ __forceinline__ void bsplit(float v, __nv_bfloat16& h, __nv_bfloat16& l) {
    h = __float2bfloat16_rn(v);
    l = __float2bfloat16_rn(v - __bfloat162float(h));
}

#define MMA_BF16(c, a, b)                                                        \
    asm volatile("mma.sync.aligned.m16n8k16.row.col.f32.bf16.bf16.f32 "          \
                 "{%0,%1,%2,%3}, {%4,%5,%6,%7}, {%8,%9}, {%0,%1,%2,%3};\n"       \
                 : "+f"((c)[0]), "+f"((c)[1]), "+f"((c)[2]), "+f"((c)[3])        \
                 : "r"((a)[0]), "r"((a)[1]), "r"((a)[2]), "r"((a)[3]),           \
                   "r"((b)[0]), "r"((b)[1]))

// ====== GEMM1 (3xBF16 split, m16n8k16, single buffer, 2 CTAs/SM) =============
#define SSTRB 136
__global__ void __launch_bounds__(256, 2) gemm1_k(
    const float* __restrict__ A, const float* __restrict__ Bsrc,
    const float* __restrict__ bias, float* __restrict__ C)
{
    __shared__ unsigned int Ah[8][SSTRB], Al[8][SSTRB];
    __shared__ unsigned int Bh[8][SSTRB], Bl[8][SSTRB];
    __shared__ float redS[2][64][4], redQ[2][64][4];

    const int bb = blockIdx.z;
    const int n0 = blockIdx.x * 128;
    const int m0 = blockIdx.y * 128;
    const float* Bp = Bsrc + (size_t)bb * DD * HW;
    const int tid = threadIdx.x;
    const int wid = tid >> 5, lane = tid & 31;
    const int wm = wid >> 2, wn = wid & 3;
    const int g = lane >> 2, tg = lane & 3;

    const int arow = tid >> 1, ak2 = (tid & 1) * 4;
    const int br = tid >> 5;

    float c[4][4][4] = {};
    float4 pa0, pa1;
    float bB0[4], bB1[4];

    pa0 = *(const float4*)&A[(m0 + arow) * DD + ak2 * 2];
    pa1 = *(const float4*)&A[(m0 + arow) * DD + ak2 * 2 + 4];
#pragma unroll
    for (int q = 0; q < 4; q++) {
        bB0[q] = Bp[(size_t)(2 * br) * HW + n0 + lane + 32 * q];
        bB1[q] = Bp[(size_t)(2 * br + 1) * HW + n0 + lane + 32 * q];
    }

    for (int k0 = 0; k0 < DD; k0 += 16) {
        // ---- stage: split fp32 -> bf16 hi/lo, pack k-pairs ----
        {
            float av[8] = {pa0.x, pa0.y, pa0.z, pa0.w, pa1.x, pa1.y, pa1.z, pa1.w};
#pragma unroll
            for (int p = 0; p < 4; p++) {
                __nv_bfloat16 h0, l0, h1, l1;
                bsplit(av[2 * p], h0, l0);
                bsplit(av[2 * p + 1], h1, l1);
                Ah[ak2 + p][arow] = packb(h0, h1);
                Al[ak2 + p][arow] = packb(l0, l1);
            }
#pragma unroll
            for (int q = 0; q < 4; q++) {
                __nv_bfloat16 h0, l0, h1, l1;
                bsplit(bB0[q], h0, l0);
                bsplit(bB1[q], h1, l1);
                Bh[br][lane + 32 * q] = packb(h0, h1);
                Bl[br][lane + 32 * q] = packb(l0, l1);
            }
        }
        __syncthreads();
        // ---- prefetch next slab ----
        if (k0 + 16 < DD) {
            pa0 = *(const float4*)&A[(m0 + arow) * DD + k0 + 16 + ak2 * 2];
            pa1 = *(const float4*)&A[(m0 + arow) * DD + k0 + 16 + ak2 * 2 + 4];
#pragma unroll
            for (int q = 0; q < 4; q++) {
                bB0[q] = Bp[(size_t)(k0 + 16 + 2 * br) * HW + n0 + lane + 32 * q];
                bB1[q] = Bp[(size_t)(k0 + 16 + 2 * br + 1) * HW + n0 + lane + 32 * q];
            }
        }
        // ---- fragments + MMA ----
        {
            unsigned int ah[4][4], alr[4][4], bhf[4][2], blf[4][2];
#pragma unroll
            for (int i = 0; i < 4; i++) {
                int m = wm * 64 + i * 16 + g;
                ah[i][0] = Ah[tg][m];     ah[i][1] = Ah[tg][m + 8];
                ah[i][2] = Ah[tg + 4][m]; ah[i][3] = Ah[tg + 4][m + 8];
                alr[i][0] = Al[tg][m];     alr[i][1] = Al[tg][m + 8];
                alr[i][2] = Al[tg + 4][m]; alr[i][3] = Al[tg + 4][m + 8];
            }
#pragma unroll
            for (int j = 0; j < 4; j++) {
                int n = wn * 32 + j * 8 + g;
                bhf[j][0] = Bh[tg][n]; bhf[j][1] = Bh[tg + 4][n];
                blf[j][0] = Bl[tg][n]; blf[j][1] = Bl[tg + 4][n];
            }
#pragma unroll
            for (int i = 0; i < 4; i++)
#pragma unroll
                for (int j = 0; j < 4; j++) {
                    MMA_BF16(c[i][j], ah[i], bhf[j]);
                    MMA_BF16(c[i][j], ah[i], blf[j]);
                    MMA_BF16(c[i][j], alr[i], bhf[j]);
                }
        }
        __syncthreads();
    }
    // ---- epilogue: bias + store + BN partials ----
#pragma unroll
    for (int i = 0; i < 4; i++) {
        int m = m0 + wm * 64 + i * 16 + g;
        float bs0 = bias[m], bs1 = bias[m + 8];
#pragma unroll
        for (int j = 0; j < 4; j++) {
            c[i][j][0] += bs0; c[i][j][1] += bs0;
            c[i][j][2] += bs1; c[i][j][3] += bs1;
            int n = n0 + wn * 32 + j * 8 + 2 * tg;
            float2 o0 = {c[i][j][0], c[i][j][1]};
            float2 o1 = {c[i][j][2], c[i][j][3]};
            *(float2*)&C[(size_t)(bb * DD + m) * HW + n] = o0;
            *(float2*)&C[(size_t)(bb * DD + m + 8) * HW + n] = o1;
        }
    }
#pragma unroll
    for (int i = 0; i < 4; i++) {
        float s0 = 0.f, s1 = 0.f, q0 = 0.f, q1 = 0.f;
#pragma unroll
        for (int j = 0; j < 4; j++) {
            s0 += c[i][j][0] + c[i][j][1];
            q0 += c[i][j][0] * c[i][j][0] + c[i][j][1] * c[i][j][1];
            s1 += c[i][j][2] + c[i][j][3];
            q1 += c[i][j][2] * c[i][j][2] + c[i][j][3] * c[i][j][3];
        }
#pragma unroll
        for (int o = 1; o <= 2; o <<= 1) {
            s0 += __shfl_xor_sync(0xffffffffu, s0, o);
            s1 += __shfl_xor_sync(0xffffffffu, s1, o);
            q0 += __shfl_xor_sync(0xffffffffu, q0, o);
            q1 += __shfl_xor_sync(0xffffffffu, q1, o);
        }
        if (tg == 0) {
            redS[wm][i * 16 + g][wn] = s0;
            redS[wm][i * 16 + g + 8][wn] = s1;
            redQ[wm][i * 16 + g][wn] = q0;
            redQ[wm][i * 16 + g + 8][wn] = q1;
        }
    }
    __syncthreads();
    if (tid < 128) {
        int wmx = tid >> 6, r = tid & 63;
        float s = redS[wmx][r][0] + redS[wmx][r][1] + redS[wmx][r][2] + redS[wmx][r][3];
        float q = redQ[wmx][r][0] + redQ[wmx][r][1] + redQ[wmx][r][2] + redQ[wmx][r][3];
        int pidx = blockIdx.z * 128 + blockIdx.x;
        g_psum[pidx * DD + m0 + tid] = s;
        g_psq [pidx * DD + m0 + tid] = q;
    }
}

// ---------------- BN scale/shift ----------------
__global__ void __launch_bounds__(128) bnscale_k(const float* __restrict__ gamma,
                                                 const float* __restrict__ beta)
{
    __shared__ float ssh[4], qsh[4];
    const int e = blockIdx.x;
    float s = 0.f, q = 0.f;
    for (int p = threadIdx.x; p < NPART; p += 128) {
        s += g_psum[p * DD + e];
        q += g_psq [p * DD + e];
    }
    int lane = threadIdx.x & 31, w = threadIdx.x >> 5;
    s = warpSumF(s); q = warpSumF(q);
    if (lane == 0) { ssh[w] = s; qsh[w] = q; }
    __syncthreads();
    if (threadIdx.x == 0) {
        float ts = ssh[0] + ssh[1] + ssh[2] + ssh[3];
        float tq = qsh[0] + qsh[1] + qsh[2] + qsh[3];
        const float inv_n = 1.f / (float)(NB * HW);
        float mean = ts * inv_n;
        float var  = tq * inv_n - mean * mean;
        float sc = gamma[e] * rsqrtf(var + 1e-5f);
        g_scale[e] = sc;
        g_shift[e] = beta[e] - mean * sc;
    }
}

// ---------------- masks ----------------
__global__ void mask_k(const int* __restrict__ labels, const float* __restrict__ po,
                       const float* __restrict__ pa, const float* __restrict__ unc)
{
    int i = blockIdx.x * blockDim.x + threadIdx.x;
    if (i >= NB * HW) return;
    int b = i >> 14, hw = i & (HW - 1);
    const float* o = po + (size_t)b * 2 * HW;
    const float* a = pa + (size_t)b * 2 * HW;
    int ao = (o[HW + hw] > o[hw]) ? 1 : 0;
    int aa = (a[HW + hw] > a[hw]) ? 1 : 0;
    bool valid = (ao == aa) && (unc[i] > 0.5f);
    unsigned char m = 0;
    if (valid) m = (labels[i] == 1) ? 1 : 2;
    g_mask[i] = m;
}

// ---------------- masked sums of y ----------------
__global__ void __launch_bounds__(256) ymask_k()
{
    __shared__ float s1[8], s2[8];
    const int d = blockIdx.x, b = blockIdx.y;
    const float* row = g_x + (size_t)(b * DD + d) * HW;
    const unsigned char* mk = g_mask + b * HW;
    const float sc = g_scale[d], sh = g_shift[d];
    float sf = 0.f, sb = 0.f;
    for (int i = threadIdx.x; i < HW; i += 256) {
        float y = fmaxf(fmaf(sc, row[i], sh), 0.f);
        unsigned char m = mk[i];
        sf += (m == 1) ? y : 0.f;
        sb += (m == 2) ? y : 0.f;
    }
    int lane = threadIdx.x & 31, w = threadIdx.x >> 5;
    sf = warpSumF(sf); sb = warpSumF(sb);
    if (lane == 0) { s1[w] = sf; s2[w] = sb; }
    __syncthreads();
    if (threadIdx.x == 0) {
        float a = 0.f, bb = 0.f;
        for (int i = 0; i < 8; i++) { a += s1[i]; bb += s2[i]; }
        g_syf[b * DD + d] = a;
        g_syb[b * DD + d] = bb;
    }
}

// ---------------- w2 transpose ----------------
__global__ void w2t_k(const float* __restrict__ w2)
{
    int k = blockIdx.x, m = threadIdx.x;
    g_w2t[k * DD + m] = w2[m * DD + k];
}

// ================= selection: radix top-k ==========
struct SelShared {
    int hist[256];
    int warp_tot[17];
    int s_bin, s_rem, s_ngt, s_fill, s_mcnt;
    int sel_idx[NC2];
    unsigned int sel_key[NC2];
    int cand_idx[NC2];
    float cand_w[NC2];
    unsigned long long sbuf[NC2];
};

__device__ __forceinline__ int blk_scan(int pred, int* warp_tot, int tid, int* tot) {
    unsigned bal = __ballot_sync(0xffffffffu, pred);
    int lane = tid & 31, w = tid >> 5;
    if (lane == 0) warp_tot[w] = __popc(bal);
    __syncthreads();
    if (tid == 0) {
        int s = 0;
        for (int i = 0; i < 16; i++) { int t = warp_tot[i]; warp_tot[i] = s; s += t; }
        warp_tot[16] = s;
    }
    __syncthreads();
    int rank = warp_tot[w] + __popc(bal & ((1u << lane) - 1));
    *tot = warp_tot[16];
    __syncthreads();
    return rank;
}

__device__ void topk_sel(unsigned int* skey, int k, SelShared* sh, int tid, bool want_cnt) {
    unsigned int prefix = 0;
    if (tid == 0) sh->s_rem = k;
    __syncthreads();
#pragma unroll
    for (int level = 0; level < 4; level++) {
        int shift = 24 - 8 * level;
        if (tid < 256) sh->hist[tid] = 0;
        __syncthreads();
        for (int i = tid; i < HW; i += 512) {
            unsigned int v = skey[i];
            bool in = (level == 0) || ((v >> (shift + 8)) == prefix);
            if (in) atomicAdd(&sh->hist[(v >> shift) & 255], 1);
        }
        __syncthreads();
        if (tid == 0) {
            if (level == 0 && want_cnt) {
                int mc = 0;
                for (int b = 128; b < 256; b++) mc += sh->hist[b];
                sh->s_mcnt = mc;
            }
            int need = sh->s_rem;
            int c = 0, b;
            for (b = 255; b >= 0; --b) {
                int h = sh->hist[b];
                if (c + h >= need) break;
                c += h;
            }
            sh->s_bin = b;
            sh->s_rem = need - c;
        }
        __syncthreads();
        prefix = (prefix << 8) | (unsigned int)sh->s_bin;
        __syncthreads();
    }
    const unsigned int T = prefix;
    const int rem = sh->s_rem;
    if (tid == 0) sh->s_ngt = 0;
    __syncthreads();
    for (int i = tid; i < HW; i += 512) {
        unsigned int v = skey[i];
        if (v > T) {
            int p = atomicAdd(&sh->s_ngt, 1);
            sh->sel_idx[p] = i;
            sh->sel_key[p] = v;
        }
    }
    __syncthreads();
    const int cgt = sh->s_ngt;
    if (tid == 0) sh->s_fill = 0;
    __syncthreads();
    if (rem > 0) {
        for (int base = 0; base < HW; base += 512) {
            int i = base + tid;
            int pred = (skey[i] == T) ? 1 : 0;
            int tot;
            int rank = blk_scan(pred, sh->warp_tot, tid, &tot);
            int fl = sh->s_fill;
            if (pred && fl + rank < rem) {
                sh->sel_idx[cgt + fl + rank] = i;
                sh->sel_key[cgt + fl + rank] = T;
            }
            __syncthreads();
            if (tid == 0) sh->s_fill += tot;
            __syncthreads();
            if (sh->s_fill >= rem) break;
            __syncthreads();
        }
    }
    __syncthreads();
}

__device__ void bitonic128(unsigned long long* buf, int tid) {
    for (int ksz = 2; ksz <= 128; ksz <<= 1)
        for (int j = ksz >> 1; j > 0; j >>= 1) {
            __syncthreads();
            if (tid < 64) {
                int i = ((tid / j) * (j << 1)) + (tid & (j - 1));
                int ixj = i + j;
                bool up = ((i & ksz) == 0);
                unsigned long long x = buf[i], y = buf[ixj];
                if ((x > y) == up) { buf[i] = y; buf[ixj] = x; }
            }
        }
    __syncthreads();
}

// blockIdx.x = bc*3 + phase; phase 0 = anchors, 1 = pos, 2 = neg
__global__ void __launch_bounds__(512) select3_k(
    const float* __restrict__ r_anc, const float* __restrict__ r_pos,
    const float* __restrict__ r_neg, const float* __restrict__ unc)
{
    extern __shared__ unsigned int skey[];
    __shared__ SelShared sh;
    const int bc = blockIdx.x / 3, phase = blockIdx.x - bc * 3;
    const int b = bc >> 1, c = bc & 1;
    const unsigned char wantA = (c == 0) ? 1 : 2;
    const unsigned char wantN = (c == 0) ? 2 : 1;
    const unsigned char* mk = g_mask + b * HW;
    const int tid = threadIdx.x;

    if (phase == 0) {
        const float* r = r_anc + (size_t)bc * HW;
        for (int i = tid; i < HW; i += 512)
            skey[i] = (mk[i] == wantA) ? ford(r[i]) : 0u;
        __syncthreads();
        topk_sel(skey, NR, &sh, tid, true);
        if (tid == 0) g_cntA[bc] = sh.s_mcnt;
        if (tid < NR) {
            g_aidx[bc * NR + tid] = sh.sel_idx[tid];
            g_aw  [bc * NR + tid] = (sh.sel_key[tid] >= 0x80000000u) ? 1.f : 0.f;
        }
        return;
    }

    const int ph = phase - 1;
    const unsigned char want = ph ? wantN : wantA;
    const float* r = (ph ? r_neg : r_pos) + (size_t)bc * HW;
    for (int i = tid; i < HW; i += 512)
        skey[i] = (mk[i] == want) ? ford(r[i]) : 0u;
    __syncthreads();
    topk_sel(skey, NC2, &sh, tid, ph == 1);
    if (ph == 1 && tid == 0) g_cntN[bc] = sh.s_mcnt;
    if (tid < NC2)
        sh.sbuf[tid] = ((unsigned long long)sh.sel_key[tid] << 32) |
                       (unsigned int)(~sh.sel_idx[tid]);
    __syncthreads();
    bitonic128(sh.sbuf, tid);
    if (tid < NC2) {
        unsigned long long e = sh.sbuf[127 - tid];
        int idx = (int)(~(unsigned int)(e & 0xFFFFFFFFu));
        unsigned int kv = (unsigned int)(e >> 32);
        sh.cand_idx[tid] = idx;
        sh.cand_w[tid] = (kv >= 0x80000000u) ? 1.f : 0.f;
    }
    __syncthreads();
    if (tid < NC2) {
        unsigned int uk = (sh.cand_w[tid] > 0.f)
                        ? ford(unc[b * HW + sh.cand_idx[tid]]) : 0u;
        sh.sbuf[tid] = ((unsigned long long)uk << 32) |
                       (unsigned int)(0xFFFFFFFFu - (unsigned int)tid);
    }
    __syncthreads();
    bitonic128(sh.sbuf, tid);
    int*   oidx = ph ? g_nidx : g_pidx;
    float* ow   = ph ? g_nw   : g_pw;
    if (tid < NS) {
        unsigned long long e = sh.sbuf[127 - tid];
        int t = (int)(0xFFFFFFFFu - (unsigned int)(e & 0xFFFFFFFFu));
        oidx[bc * NS + tid] = sh.cand_idx[t];
        ow  [bc * NS + tid] = sh.cand_w[t];
    }
}

// ---------------- project selected pixels ----------------
__global__ void __launch_bounds__(256) psel_k(const float* __restrict__ b2)
{
    __shared__ float ys[4][DD];
    const int bc = blockIdx.y, b = bc >> 1;
    const int col0 = blockIdx.x * 4;
    const int tid = threadIdx.x;
    const float sc = g_scale[tid], sh = g_shift[tid];
#pragma unroll
    for (int cc = 0; cc < 4; cc++) {
        int col = col0 + cc;
        int idx;
        if (col < 32)      idx = g_aidx[bc * NR + col];
        else if (col < 96) idx = g_pidx[bc * NS + col - 32];
        else               idx = g_nidx[bc * NS + col - 96];
        float x = g_x[(size_t)(b * DD + tid) * HW + idx];
        ys[cc][tid] = fmaxf(fmaf(sc, x, sh), 0.f);
    }
    __syncthreads();
    float acc0, acc1, acc2, acc3;
    acc0 = acc1 = acc2 = acc3 = b2[tid];
    for (int k = 0; k < DD; k++) {
        float w = g_w2t[k * DD + tid];
        acc0 = fmaf(w, ys[0][k], acc0);
        acc1 = fmaf(w, ys[1][k], acc1);
        acc2 = fmaf(w, ys[2][k], acc2);
        acc3 = fmaf(w, ys[3][k], acc3);
    }
    float* outp = g_psel + ((size_t)bc * NSEL + col0) * DD;
    outp[0 * DD + tid] = acc0;
    outp[1 * DD + tid] = acc1;
    outp[2 * DD + tid] = acc2;
    outp[3 * DD + tid] = acc3;
}

// ---------------- pair loss ----------------
__global__ void __launch_bounds__(256) pair_k()
{
    __shared__ float q[NR][DD];
    __shared__ float pnw[8][NR];
    const int bc = blockIdx.x;
    const int tid = threadIdx.x, lane = tid & 31, w = tid >> 5;
    const float* ps = g_psel + (size_t)bc * NSEL * DD;

    for (int a = w; a < NR; a += 8) {
        float vv[8]; float ss = 0.f;
#pragma unroll
        for (int j = 0; j < 8; j++) {
            float v = ps[a * DD + lane + 32 * j];
            vv[j] = v; ss = fmaf(v, v, ss);
        }
        ss = warpSumF(ss);
        float inv = 1.f / fmaxf(sqrtf(ss), 1e-12f);
#pragma unroll
        for (int j = 0; j < 8; j++) q[a][lane + 32 * j] = vv[j] * inv;
    }
    pnw[w][lane] = 0.f;
    __syncthreads();

    const int ph = w >> 2, lw = w & 3;
    const float* wl = ph ? g_nw : g_pw;
    const int colbase = ph ? 96 : 32;
    for (int t = 0; t < 16; t++) {
        int s = lw * 16 + t;
        const float* vp = ps + (colbase + s) * DD;
        float vv[8]; float ss = 0.f;
#pragma unroll
        for (int j = 0; j < 8; j++) {
            float v = vp[lane + 32 * j];
            vv[j] = v; ss = fmaf(v, v, ss);
        }
        ss = warpSumF(ss);
        float inv = 1.f / fmaxf(sqrtf(ss), 1e-12f);
        float wt = wl[bc * NS + s];
#pragma unroll
        for (int a = 0; a < NR; a++) {
            float ds = 0.f;
#pragma unroll
            for (int j = 0; j < 8; j++)
                ds = fmaf(vv[j], q[a][lane + 32 * j], ds);
            ds = warpSumF(ds);
            if (lane == 0) pnw[w][a] += expf(ds * inv * INVTAU) * wt;
        }
    }
    __syncthreads();

    if (tid < 32) {
        int inc = (g_cntA[bc] >= 1 && g_cntN[bc] >= 1) ? 1 : 0;
        float p = pnw[0][tid] + pnw[1][tid] + pnw[2][tid] + pnw[3][tid]
                + (inc ? 0.f : 1.f);
        float n = pnw[4][tid] + pnw[5][tid] + pnw[6][tid] + pnw[7][tid];
        float per = -logf(p / (p + n + 1e-8f));
        float af = g_aw[bc * NR + tid];
        float num = warpSumF(per * af);
        float den = warpSumF(af);
        if (tid == 0) {
            float bl = num / fmaxf(den, 1.f);
            g_bl[bc] = inc ? bl : 0.f;
            g_inc[bc] = inc;
        }
    }
}

// ---------------- final ----------------
__global__ void __launch_bounds__(256) final_k(const float* __restrict__ b2,
                                               float* __restrict__ out)
{
    __shared__ float sy[8][DD];
    __shared__ float qv[8][DD];
    __shared__ float selfd[8], Xs[16];
    __shared__ float cfa[NB], cba[NB];
    __shared__ int vg[NB];
    const int tid = threadIdx.x, lane = tid & 31, w = tid >> 5;

    if (tid < NB) {
        int a = g_cntA[tid * 2], bb = g_cntN[tid * 2];
        cfa[tid] = (float)a; cba[tid] = (float)bb;
        vg[tid] = (a >= 1 && bb >= 1) ? 1 : 0;
    }
    __syncthreads();
#pragma unroll
    for (int v = 0; v < 8; v++) {
        int s = v >> 2, b = v & 3;
        float cnt = s ? cba[b] : cfa[b];
        const float* src = s ? (g_syb + b * DD) : (g_syf + b * DD);
        sy[v][tid] = src[tid] / fmaxf(cnt, 1.f);
    }
    __syncthreads();
    float acc[8];
    float bv = b2[tid];
#pragma unroll
    for (int v = 0; v < 8; v++) acc[v] = bv;
    for (int k = 0; k < DD; k++) {
        float wv = g_w2t[k * DD + tid];
#pragma unroll
        for (int v = 0; v < 8; v++) acc[v] = fmaf(wv, sy[v][k], acc[v]);
    }
#pragma unroll
    for (int v = 0; v < 8; v++) qv[v][tid] = acc[v];
    __syncthreads();
    {
        float ss = 0.f;
#pragma unroll
        for (int j = 0; j < 8; j++) {
            float x = qv[w][lane + 32 * j];
            ss = fmaf(x, x, ss);
        }
        ss = warpSumF(ss);
        float inv = 1.f / fmaxf(sqrtf(ss), 1e-12f);
#pragma unroll
        for (int j = 0; j < 8; j++) qv[w][lane + 32 * j] *= inv;
        __syncwarp();
        float s2 = 0.f;
#pragma unroll
        for (int j = 0; j < 8; j++) {
            float x = qv[w][lane + 32 * j];
            s2 = fmaf(x, x, s2);
        }
        s2 = warpSumF(s2);
        if (lane == 0) selfd[w] = s2;
    }
    __syncthreads();
    for (int pi = w; pi < 16; pi += 8) {
        int j = pi >> 2, b = pi & 3;
        float ds = 0.f;
#pragma unroll
        for (int jj = 0; jj < 8; jj++)
            ds = fmaf(qv[4 + j][lane + 32 * jj], qv[b][lane + 32 * jj], ds);
        ds = warpSumF(ds);
        if (lane == 0) Xs[pi] = ds;
    }
    __syncthreads();
    if (tid == 0) {
        float lg_sum = 0.f; int vg_cnt = 0;
        for (int b = 0; b < NB; b++) {
            float nf = 0.f, nbv = 0.f;
            for (int j = 0; j <= b; j++)
                if (vg[j]) {
                    nf  += expf(Xs[j * 4 + b] * INVTAU);
                    nbv += expf(Xs[b * 4 + j] * INVTAU);
                }
            float pf = expf(selfd[b] * INVTAU);
            float pb = expf(selfd[4 + b] * INVTAU);
            float lg = -logf(pf / (pf + nf + 1e-8f)) - logf(pb / (pb + nbv + 1e-8f));
            if (vg[b]) { lg_sum += lg; vg_cnt++; }
        }
        float l_global = lg_sum / fmaxf((float)vg_cnt, 1.f);
        float bl_sum = 0.f; int inc_cnt = 0;
        for (int i = 0; i < NB * 2; i++) { bl_sum += g_bl[i]; inc_cnt += g_inc[i]; }
        float l_local = bl_sum / fmaxf((float)inc_cnt, 1.f);
        out[0] = l_local + 0.5f * l_global;
        out[1] = l_local;
        out[2] = l_global;
    }
}

// ---------------- launch ----------------
extern "C" void kernel_launch(void* const* d_in, const int* in_sizes, int n_in,
                              void* d_out, int out_size)
{
    const float* feat   = (const float*)d_in[0];
    const int*   labels = (const int*)  d_in[1];
    const float* po     = (const float*)d_in[2];
    const float* pa     = (const float*)d_in[3];
    const float* unc    = (const float*)d_in[4];
    const float* r_anc  = (const float*)d_in[5];
    const float* r_pos  = (const float*)d_in[6];
    const float* r_neg  = (const float*)d_in[7];
    const float* w1     = (const float*)d_in[8];
    const float* b1     = (const float*)d_in[9];
    const float* gamma  = (const float*)d_in[10];
    const float* beta   = (const float*)d_in[11];
    const float* w2     = (const float*)d_in[12];
    const float* b2     = (const float*)d_in[13];
    float* out = (float*)d_out;

    static cudaStream_t s2 = nullptr;
    static cudaEvent_t evRoot = nullptr, evM = nullptr, evMask = nullptr, evJ2 = nullptr;
    if (!s2) {
        cudaStreamCreateWithFlags(&s2, cudaStreamNonBlocking);
        cudaEventCreateWithFlags(&evRoot, cudaEventDisableTiming);
        cudaEventCreateWithFlags(&evM, cudaEventDisableTiming);
        cudaEventCreateWithFlags(&evMask, cudaEventDisableTiming);
        cudaEventCreateWithFlags(&evJ2, cudaEventDisableTiming);
        cudaFuncSetAttribute(select3_k, cudaFuncAttributeMaxDynamicSharedMemorySize,
                             HW * (int)sizeof(unsigned int));
    }

    void* px = nullptr;
    cudaGetSymbolAddress(&px, g_x);

    // fork side stream
    cudaEventRecord(evRoot, 0);
    cudaStreamWaitEvent(s2, evRoot, 0);

    // main stream: GEMM + BN reduce
    gemm1_k<<<dim3(HW / 128, DD / 128, NB), 256>>>(w1, feat, b1, (float*)px);
    bnscale_k<<<DD, 128>>>(gamma, beta);
    cudaEventRecord(evM, 0);

    // side stream: input-only chain, then selected-pixel projection + pair loss
    mask_k<<<(NB * HW + 255) / 256, 256, 0, s2>>>(labels, po, pa, unc);
    cudaEventRecord(evMask, s2);
    select3_k<<<NB * 2 * 3, 512, HW * (int)sizeof(unsigned int), s2>>>(r_anc, r_pos, r_neg, unc);
    w2t_k<<<DD, DD, 0, s2>>>(w2);
    cudaStreamWaitEvent(s2, evM, 0);
    psel_k<<<dim3(NSEL / 4, NB * 2), 256, 0, s2>>>(b2);
    pair_k<<<NB * 2, 256, 0, s2>>>();
    cudaEventRecord(evJ2, s2);

    // main stream: masked sums (overlaps psel/pair), then final combine
    cudaStreamWaitEvent(0, evMask, 0);
    ymask_k<<<dim3(DD, NB), 256>>>();
    cudaStreamWaitEvent(0, evJ2, 0);
    final_k<<<1, 256>>>(b2, out);
}